// round 7
// baseline (speedup 1.0000x reference)
#include <cuda_runtime.h>
#include <cuda_bf16.h>
#include <cuda_fp8.h>
#include <cstdint>

// ============================================================================
// ContrastiveLoss (N=4096, D=256, tau=0.1)
//   z = normalize(concat(x1,x2)) -> e4m3
//   denom[r] = sum_j exp(mask * (z_r . z_j) / tau)   (diag -> exp(0)=1)
//   loss = mean_r( log(denom[r]) - pos[r]/tau )      (pos in exact fp32)
// Symmetric-triangle fused FP8 mma.sync GEMM. 128x32 tiles, warp tile 16x32,
// ring-3 B buffers with ONE __syncthreads per tile, 3 CTAs/SM.
// ============================================================================

#define TAU_INV 10.0f
static constexpr int NROWS = 4096;
static constexpr int TWO_N = 8192;
static constexpr int D     = 256;          // K
static constexpr int BM    = 128;          // rows per strip
static constexpr int BN    = 32;           // cols per tile
// tiles (I strip of 128 rows, J 32-col block), J32 >= 4I.
// pair p in [0,32): strip p (256-4p tiles) + strip 63-p (4p+4 tiles) = 260.
static constexpr int NUM_TILES = 8320;
static constexpr int NUM_CTAS  = 444;                // 3 per SM
static constexpr int K_STEPS   = D / 32;             // 8 (fp8 k=32 per mma)
static constexpr int NTHREADS  = 256;

// SMEM: padded row stride 272 B (17 x 16B)
static constexpr int TSTRIDE_B = 272;
static constexpr int A_TILE_BYTES = BM * TSTRIDE_B;   // 34816
static constexpr int B_TILE_BYTES = BN * TSTRIDE_B;   // 8704
static constexpr int SMEM_TOTAL = A_TILE_BYTES + 3 * B_TILE_BYTES;  // 60928

// ---------------- device scratch (allocation-free) --------------------------
__device__ unsigned char g_z8[TWO_N * D];   // e4m3, row-major [8192][256]  (2 MB)
__device__ float    g_pos[NROWS];
__device__ float    g_denom[TWO_N];
__device__ unsigned g_done;

// ---------------- PTX helpers ----------------------------------------------
__device__ __forceinline__ uint32_t smem_to_u32(const void* p) {
    uint32_t a;
    asm("{ .reg .u64 t; cvta.to.shared.u64 t, %1; cvt.u32.u64 %0, t; }"
        : "=r"(a) : "l"(p));
    return a;
}

__device__ __forceinline__ void cp_async16(uint32_t dst, const void* src) {
    asm volatile("cp.async.cg.shared.global [%0], [%1], 16;"
                 :: "r"(dst), "l"(src) : "memory");
}
#define CP_COMMIT() asm volatile("cp.async.commit_group;" ::: "memory")
#define CP_WAIT1()  asm volatile("cp.async.wait_group 1;" ::: "memory")

__device__ __forceinline__ void ldsm_x4(uint32_t* r, uint32_t addr) {
    asm volatile("ldmatrix.sync.aligned.m8n8.x4.shared.b16 {%0,%1,%2,%3}, [%4];"
                 : "=r"(r[0]), "=r"(r[1]), "=r"(r[2]), "=r"(r[3]) : "r"(addr));
}

// FP8 e4m3 MMA m16n8k32; fragments follow the (validated) ldmatrix b16 layout.
#define MMA16832F8(d, a, bx, by) \
    asm volatile( \
        "mma.sync.aligned.m16n8k32.row.col.f32.e4m3.e4m3.f32 " \
        "{%0,%1,%2,%3}, {%4,%5,%6,%7}, {%8,%9}, {%0,%1,%2,%3};" \
        : "+f"((d)[0]), "+f"((d)[1]), "+f"((d)[2]), "+f"((d)[3]) \
        : "r"((a)[0]), "r"((a)[1]), "r"((a)[2]), "r"((a)[3]), \
          "r"(bx), "r"(by))

__device__ __forceinline__ uint32_t pack_e4m3x4(float v0, float v1, float v2, float v3) {
    __nv_fp8x2_storage_t lo =
        __nv_cvt_float2_to_fp8x2(make_float2(v0, v1), __NV_SATFINITE, __NV_E4M3);
    __nv_fp8x2_storage_t hi =
        __nv_cvt_float2_to_fp8x2(make_float2(v2, v3), __NV_SATFINITE, __NV_E4M3);
    return (uint32_t)lo | ((uint32_t)hi << 16);
}

// ---------------- Stage 1: fused normalize + pos (reads x1/x2 once) --------
__global__ void normpos_kernel(const float* __restrict__ x1, const float* __restrict__ x2) {
    int i    = blockIdx.x * 8 + (threadIdx.x >> 5);   // pair row 0..4095
    int lane = threadIdx.x & 31;
    if (blockIdx.x == 0 && threadIdx.x == 0) g_done = 0;

    const float4* s1 = reinterpret_cast<const float4*>(x1 + (size_t)i * D);
    const float4* s2 = reinterpret_cast<const float4*>(x2 + (size_t)i * D);
    float4 a0 = s1[lane * 2], a1 = s1[lane * 2 + 1];
    float4 b0 = s2[lane * 2], b1 = s2[lane * 2 + 1];

    float ss1 = a0.x * a0.x + a0.y * a0.y + a0.z * a0.z + a0.w * a0.w
              + a1.x * a1.x + a1.y * a1.y + a1.z * a1.z + a1.w * a1.w;
    float ss2 = b0.x * b0.x + b0.y * b0.y + b0.z * b0.z + b0.w * b0.w
              + b1.x * b1.x + b1.y * b1.y + b1.z * b1.z + b1.w * b1.w;
    float dot = a0.x * b0.x + a0.y * b0.y + a0.z * b0.z + a0.w * b0.w
              + a1.x * b1.x + a1.y * b1.y + a1.z * b1.z + a1.w * b1.w;
    #pragma unroll
    for (int o = 16; o; o >>= 1) {
        ss1 += __shfl_xor_sync(0xffffffffu, ss1, o);
        ss2 += __shfl_xor_sync(0xffffffffu, ss2, o);
        dot += __shfl_xor_sync(0xffffffffu, dot, o);
    }
    float inv1 = 1.0f / fmaxf(sqrtf(ss1), 1e-12f);
    float inv2 = 1.0f / fmaxf(sqrtf(ss2), 1e-12f);
    if (lane == 0) {
        g_pos[i] = dot * inv1 * inv2;
        g_denom[i] = 0.0f;
        g_denom[i + NROWS] = 0.0f;
    }

    uint2 w1, w2;
    w1.x = pack_e4m3x4(a0.x * inv1, a0.y * inv1, a0.z * inv1, a0.w * inv1);
    w1.y = pack_e4m3x4(a1.x * inv1, a1.y * inv1, a1.z * inv1, a1.w * inv1);
    w2.x = pack_e4m3x4(b0.x * inv2, b0.y * inv2, b0.z * inv2, b0.w * inv2);
    w2.y = pack_e4m3x4(b1.x * inv2, b1.y * inv2, b1.z * inv2, b1.w * inv2);
    *reinterpret_cast<uint2*>(g_z8 + (size_t)i * D + lane * 8) = w1;
    *reinterpret_cast<uint2*>(g_z8 + (size_t)(i + NROWS) * D + lane * 8) = w2;
}

// ---------------- tile loaders (fp8 rows of 256 B) ---------------------------
__device__ __forceinline__ void load_A(uint32_t dst, int row0, int tid) {
    const unsigned char* src = g_z8 + (size_t)row0 * D;
    #pragma unroll
    for (int i = 0; i < 8; i++) {
        int idx = tid + i * NTHREADS;      // 2048 chunks of 16B
        int r = idx >> 4, s = idx & 15;
        cp_async16(dst + r * TSTRIDE_B + s * 16, src + r * D + s * 16);
    }
}
__device__ __forceinline__ void load_B(uint32_t dst, int row0, int tid) {
    const unsigned char* src = g_z8 + (size_t)row0 * D;
    #pragma unroll
    for (int i = 0; i < 2; i++) {
        int idx = tid + i * NTHREADS;      // 512 chunks of 16B
        int r = idx >> 4, s = idx & 15;
        cp_async16(dst + r * TSTRIDE_B + s * 16, src + r * D + s * 16);
    }
}

// ---------------- Stage 2: triangular fused FP8 GEMM + exp + sums -----------
__global__ __launch_bounds__(NTHREADS, 3)
void gemm_kernel(float* __restrict__ out) {
    extern __shared__ char smem[];
    const int tid  = threadIdx.x;
    const int lane = tid & 31;
    const int warp = tid >> 5;              // 0..7, owns rows warp*16..+16
    const int cta  = blockIdx.x;

    const uint32_t smem_u = smem_to_u32(smem);
    const uint32_t A_base = smem_u;
    const uint32_t Bb0 = smem_u + A_TILE_BYTES;

    const int t0 = (int)(((long long)cta * NUM_TILES) / NUM_CTAS);
    const int t1 = (int)(((long long)(cta + 1) * NUM_TILES) / NUM_CTAS);

    const uint32_t a_off = (uint32_t)((warp * 16 + (lane & 15)) * TSTRIDE_B
                                      + (lane >> 4) * 16);
    const uint32_t b_off = (uint32_t)((lane & 15) * TSTRIDE_B + (lane >> 4) * 16);

    float denom[2] = {0, 0};                // [e>>1], rows warp*16 + (e>>1)*8 + lane>>2

    int t = t0;
    while (t < t1) {
        // decode segment: contiguous run of tiles sharing strip I
        int p   = t / 260;
        int idx = t - p * 260;
        int na  = 256 - 4 * p;
        int I, J, seg_end;
        if (idx < na) { I = p;      J = 4 * p + idx;          seg_end = 260 * p + na; }
        else          { I = 63 - p; J = 252 - 4 * p + (idx - na); seg_end = 260 * (p + 1); }
        const int te = (seg_end < t1) ? seg_end : t1;

        // segment prologue: A strip + first B tile (one group)
        load_A(A_base, I * BM, tid);
        load_B(Bb0 + (t % 3) * B_TILE_BYTES, J * BN, tid);
        CP_COMMIT();

        const int row0 = I * BM + warp * 16;

        for (; t < te; t++, J++) {
            if (t + 1 < te)
                load_B(Bb0 + ((t + 1) % 3) * B_TILE_BYTES, (J + 1) * BN, tid);
            CP_COMMIT();                     // possibly empty group
            CP_WAIT1();                      // retire group for tile t (and A)
            __syncthreads();                 // single barrier per tile

            const uint32_t Ab = A_base + a_off;
            const uint32_t Bb = Bb0 + (t % 3) * B_TILE_BYTES + b_off;

            float acc[4][4];
            #pragma unroll
            for (int ni = 0; ni < 4; ni++)
                #pragma unroll
                for (int e = 0; e < 4; e++) acc[ni][e] = 0.0f;

            #pragma unroll
            for (int ks = 0; ks < K_STEPS; ks++) {
                uint32_t a[4], b01[4], b23[4];
                ldsm_x4(a,   Ab + ks * 32);
                ldsm_x4(b01, Bb + ks * 32);
                ldsm_x4(b23, Bb + 16 * TSTRIDE_B + ks * 32);
                MMA16832F8(acc[0], a, b01[0], b01[2]);
                MMA16832F8(acc[1], a, b01[1], b01[3]);
                MMA16832F8(acc[2], a, b23[0], b23[2]);
                MMA16832F8(acc[3], a, b23[1], b23[3]);
            }

            // epilogue: exp; row sums always, col sums when off-diag block
            const bool diagblk = ((J >> 2) == I);
            const int col0 = J * BN;
            float cs[8] = {0, 0, 0, 0, 0, 0, 0, 0};
            #pragma unroll
            for (int ni = 0; ni < 4; ni++)
                #pragma unroll
                for (int e = 0; e < 4; e++) {
                    float v = __expf(acc[ni][e] * TAU_INV);
                    if (diagblk) {
                        int r = row0 + (e >> 1) * 8 + (lane >> 2);
                        int c = col0 + ni * 8 + (lane & 3) * 2 + (e & 1);
                        if (c == r) v = 1.0f;            // diag -> exp(0)
                    }
                    denom[e >> 1] += v;
                    cs[ni * 2 + (e & 1)] += v;
                }
            if (!diagblk) {
                // reduce col partials over row-carrying lane bits (2,3,4)
                #pragma unroll
                for (int k = 0; k < 8; k++) {
                    cs[k] += __shfl_xor_sync(0xffffffffu, cs[k], 4);
                    cs[k] += __shfl_xor_sync(0xffffffffu, cs[k], 8);
                    cs[k] += __shfl_xor_sync(0xffffffffu, cs[k], 16);
                }
                if (lane < 4) {
                    #pragma unroll
                    for (int k = 0; k < 8; k++)
                        atomicAdd(&g_denom[col0 + (k >> 1) * 8 + lane * 2 + (k & 1)],
                                  cs[k]);
                }
            }
        }

        // segment epilogue: flush row denominators, protect A/B for next segment
        #pragma unroll
        for (int d = 0; d < 2; d++) {
            denom[d] += __shfl_xor_sync(0xffffffffu, denom[d], 1);
            denom[d] += __shfl_xor_sync(0xffffffffu, denom[d], 2);
        }
        if ((lane & 3) == 0) {
            #pragma unroll
            for (int d = 0; d < 2; d++)
                atomicAdd(&g_denom[row0 + d * 8 + (lane >> 2)], denom[d]);
        }
        denom[0] = denom[1] = 0.0f;
        __syncthreads();                     // all reads of A done before reload
    }

    // ---- last CTA: final log/mean reduction ----
    __threadfence();
    __shared__ unsigned s_tick;
    if (tid == 0) s_tick = atomicAdd(&g_done, 1u);
    __syncthreads();
    if (s_tick == NUM_CTAS - 1) {
        float s = 0.0f;
        for (int r = tid; r < TWO_N; r += NTHREADS)
            s += logf(g_denom[r]) - g_pos[r & (NROWS - 1)] * TAU_INV;
        #pragma unroll
        for (int o = 16; o; o >>= 1) s += __shfl_xor_sync(0xffffffffu, s, o);
        __shared__ float red[8];
        if (lane == 0) red[warp] = s;
        __syncthreads();
        if (tid == 0) {
            float v = 0.0f;
            #pragma unroll
            for (int w = 0; w < 8; w++) v += red[w];
            out[0] = v * (1.0f / (float)TWO_N);
        }
    }
}

// ---------------- launch ----------------------------------------------------
extern "C" void kernel_launch(void* const* d_in, const int* in_sizes, int n_in,
                              void* d_out, int out_size) {
    (void)in_sizes; (void)n_in; (void)out_size;
    const float* x1 = (const float*)d_in[0];
    const float* x2 = (const float*)d_in[1];
    float* out = (float*)d_out;

    cudaFuncSetAttribute(gemm_kernel,
                         cudaFuncAttributeMaxDynamicSharedMemorySize, SMEM_TOTAL);

    normpos_kernel<<<NROWS / 8, 256>>>(x1, x2);
    gemm_kernel<<<NUM_CTAS, NTHREADS, SMEM_TOTAL>>>(out);
}

// round 8
// speedup vs baseline: 1.0004x; 1.0004x over previous
#include <cuda_runtime.h>
#include <cuda_fp8.h>
#include <cstdint>

// ============================================================================
// ContrastiveLoss (N=4096, D=256, tau=0.1)
//   z = normalize(concat(x1,x2)) * sqrt(10*log2(e)) -> e4m3   (scale folded in)
//   acc = z'_r . z'_j = 14.427 * sim  ->  exp(sim/tau) = ex2(acc)
//   denom[r] = sum_j exp(...)  (diag -> exp(0)=1);  pos in exact fp32
// Triangle fused FP8 mma.sync GEMM, 128x32 tiles, warp tile 16x32,
// A fragments register-cached per strip segment, ring-3 B, 1 barrier/tile.
// ============================================================================

static constexpr int NROWS = 4096;
static constexpr int TWO_N = 8192;
static constexpr int D     = 256;          // K
static constexpr int BM    = 128;          // rows per strip
static constexpr int BN    = 32;           // cols per tile
// pair p in [0,32): strip p (256-4p tiles) + strip 63-p (4p+4 tiles) = 260.
static constexpr int NUM_TILES = 8320;
static constexpr int NUM_CTAS  = 296;                // 2 per SM
static constexpr int K_STEPS   = D / 32;             // 8 (fp8 k=32 per mma)
static constexpr int NTHREADS  = 256;

// sqrt(10 * log2(e)) — folded into z so epilogue is a bare ex2
#define ZSCALE 3.79828214f

// SMEM: padded row stride 272 B (17 x 16B)
static constexpr int TSTRIDE_B = 272;
static constexpr int A_TILE_BYTES = BM * TSTRIDE_B;   // 34816
static constexpr int B_TILE_BYTES = BN * TSTRIDE_B;   // 8704
static constexpr int SMEM_TOTAL = A_TILE_BYTES + 3 * B_TILE_BYTES;  // 60928

// ---------------- device scratch (allocation-free) --------------------------
__device__ unsigned char g_z8[TWO_N * D];   // e4m3 (pre-scaled), [8192][256]
__device__ float    g_pos[NROWS];
__device__ float    g_denom[TWO_N];
__device__ unsigned g_done;

// ---------------- PTX helpers ----------------------------------------------
__device__ __forceinline__ uint32_t smem_to_u32(const void* p) {
    uint32_t a;
    asm("{ .reg .u64 t; cvta.to.shared.u64 t, %1; cvt.u32.u64 %0, t; }"
        : "=r"(a) : "l"(p));
    return a;
}

__device__ __forceinline__ void cp_async16(uint32_t dst, const void* src) {
    asm volatile("cp.async.cg.shared.global [%0], [%1], 16;"
                 :: "r"(dst), "l"(src) : "memory");
}
#define CP_COMMIT() asm volatile("cp.async.commit_group;" ::: "memory")
#define CP_WAIT1()  asm volatile("cp.async.wait_group 1;" ::: "memory")

__device__ __forceinline__ void ldsm_x4(uint32_t* r, uint32_t addr) {
    asm volatile("ldmatrix.sync.aligned.m8n8.x4.shared.b16 {%0,%1,%2,%3}, [%4];"
                 : "=r"(r[0]), "=r"(r[1]), "=r"(r[2]), "=r"(r[3]) : "r"(addr));
}

#define MMA16832F8(d, a, bx, by) \
    asm volatile( \
        "mma.sync.aligned.m16n8k32.row.col.f32.e4m3.e4m3.f32 " \
        "{%0,%1,%2,%3}, {%4,%5,%6,%7}, {%8,%9}, {%0,%1,%2,%3};" \
        : "+f"((d)[0]), "+f"((d)[1]), "+f"((d)[2]), "+f"((d)[3]) \
        : "r"((a)[0]), "r"((a)[1]), "r"((a)[2]), "r"((a)[3]), \
          "r"(bx), "r"(by))

__device__ __forceinline__ float ex2f(float x) {
    float r;
    asm("ex2.approx.ftz.f32 %0, %1;" : "=f"(r) : "f"(x));
    return r;
}

__device__ __forceinline__ uint32_t pack_e4m3x4(float v0, float v1, float v2, float v3) {
    __nv_fp8x2_storage_t lo =
        __nv_cvt_float2_to_fp8x2(make_float2(v0, v1), __NV_SATFINITE, __NV_E4M3);
    __nv_fp8x2_storage_t hi =
        __nv_cvt_float2_to_fp8x2(make_float2(v2, v3), __NV_SATFINITE, __NV_E4M3);
    return (uint32_t)lo | ((uint32_t)hi << 16);
}

// ---------------- Stage 1: fused normalize + pos (reads x1/x2 once) --------
__global__ void normpos_kernel(const float* __restrict__ x1, const float* __restrict__ x2) {
    int i    = blockIdx.x * 8 + (threadIdx.x >> 5);   // pair row 0..4095
    int lane = threadIdx.x & 31;
    if (blockIdx.x == 0 && threadIdx.x == 0) g_done = 0;

    const float4* s1 = reinterpret_cast<const float4*>(x1 + (size_t)i * D);
    const float4* s2 = reinterpret_cast<const float4*>(x2 + (size_t)i * D);
    float4 a0 = s1[lane * 2], a1 = s1[lane * 2 + 1];
    float4 b0 = s2[lane * 2], b1 = s2[lane * 2 + 1];

    float ss1 = a0.x * a0.x + a0.y * a0.y + a0.z * a0.z + a0.w * a0.w
              + a1.x * a1.x + a1.y * a1.y + a1.z * a1.z + a1.w * a1.w;
    float ss2 = b0.x * b0.x + b0.y * b0.y + b0.z * b0.z + b0.w * b0.w
              + b1.x * b1.x + b1.y * b1.y + b1.z * b1.z + b1.w * b1.w;
    float dot = a0.x * b0.x + a0.y * b0.y + a0.z * b0.z + a0.w * b0.w
              + a1.x * b1.x + a1.y * b1.y + a1.z * b1.z + a1.w * b1.w;
    #pragma unroll
    for (int o = 16; o; o >>= 1) {
        ss1 += __shfl_xor_sync(0xffffffffu, ss1, o);
        ss2 += __shfl_xor_sync(0xffffffffu, ss2, o);
        dot += __shfl_xor_sync(0xffffffffu, dot, o);
    }
    float inv1 = 1.0f / fmaxf(sqrtf(ss1), 1e-12f);
    float inv2 = 1.0f / fmaxf(sqrtf(ss2), 1e-12f);
    if (lane == 0) {
        g_pos[i] = dot * inv1 * inv2;     // exact fp32, unscaled
        g_denom[i] = 0.0f;
        g_denom[i + NROWS] = 0.0f;
    }
    float q1 = inv1 * ZSCALE, q2 = inv2 * ZSCALE;

    uint2 w1, w2;
    w1.x = pack_e4m3x4(a0.x * q1, a0.y * q1, a0.z * q1, a0.w * q1);
    w1.y = pack_e4m3x4(a1.x * q1, a1.y * q1, a1.z * q1, a1.w * q1);
    w2.x = pack_e4m3x4(b0.x * q2, b0.y * q2, b0.z * q2, b0.w * q2);
    w2.y = pack_e4m3x4(b1.x * q2, b1.y * q2, b1.z * q2, b1.w * q2);
    *reinterpret_cast<uint2*>(g_z8 + (size_t)i * D + lane * 8) = w1;
    *reinterpret_cast<uint2*>(g_z8 + (size_t)(i + NROWS) * D + lane * 8) = w2;
}

// ---------------- tile loaders (fp8 rows of 256 B) ---------------------------
__device__ __forceinline__ void load_A(uint32_t dst, int row0, int tid) {
    const unsigned char* src = g_z8 + (size_t)row0 * D;
    #pragma unroll
    for (int i = 0; i < 8; i++) {
        int idx = tid + i * NTHREADS;      // 2048 chunks of 16B
        int r = idx >> 4, s = idx & 15;
        cp_async16(dst + r * TSTRIDE_B + s * 16, src + r * D + s * 16);
    }
}
__device__ __forceinline__ void load_B(uint32_t dst, int row0, int tid) {
    const unsigned char* src = g_z8 + (size_t)row0 * D;
    #pragma unroll
    for (int i = 0; i < 2; i++) {
        int idx = tid + i * NTHREADS;      // 512 chunks of 16B
        int r = idx >> 4, s = idx & 15;
        cp_async16(dst + r * TSTRIDE_B + s * 16, src + r * D + s * 16);
    }
}

// ---------------- Stage 2: triangular fused FP8 GEMM + ex2 + sums -----------
__global__ __launch_bounds__(NTHREADS, 2)
void gemm_kernel(float* __restrict__ out) {
    extern __shared__ char smem[];
    const int tid  = threadIdx.x;
    const int lane = tid & 31;
    const int warp = tid >> 5;              // 0..7, owns rows warp*16..+16
    const int cta  = blockIdx.x;

    const uint32_t smem_u = smem_to_u32(smem);
    const uint32_t A_base = smem_u;
    const uint32_t Bb0 = smem_u + A_TILE_BYTES;

    const int t0 = (int)(((long long)cta * NUM_TILES) / NUM_CTAS);
    const int t1 = (int)(((long long)(cta + 1) * NUM_TILES) / NUM_CTAS);

    const uint32_t a_off = (uint32_t)((warp * 16 + (lane & 15)) * TSTRIDE_B
                                      + (lane >> 4) * 16);
    const uint32_t b_off = (uint32_t)((lane & 15) * TSTRIDE_B + (lane >> 4) * 16);

    float denom[2] = {0, 0};                // rows warp*16 + d*8 + lane>>2

    int t = t0;
    while (t < t1) {
        // decode segment: contiguous run of tiles sharing strip I
        int p   = t / 260;
        int idx = t - p * 260;
        int na  = 256 - 4 * p;
        int I, J, seg_end;
        if (idx < na) { I = p;      J = 4 * p + idx;             seg_end = 260 * p + na; }
        else          { I = 63 - p; J = 252 - 4 * p + (idx - na); seg_end = 260 * (p + 1); }
        const int te = (seg_end < t1) ? seg_end : t1;

        // segment prologue: A strip + first B tile (one group)
        load_A(A_base, I * BM, tid);
        load_B(Bb0 + (t % 3) * B_TILE_BYTES, J * BN, tid);
        CP_COMMIT();

        const int row0 = I * BM + warp * 16;
        uint32_t afrag[K_STEPS][4];
        bool need_afrag = true;

        for (; t < te; t++, J++) {
            if (t + 1 < te)
                load_B(Bb0 + ((t + 1) % 3) * B_TILE_BYTES, (J + 1) * BN, tid);
            CP_COMMIT();                     // possibly empty group
            CP_WAIT1();                      // retire group for tile t (and A)
            __syncthreads();                 // single barrier per tile

            if (need_afrag) {                // once per segment: A -> registers
                #pragma unroll
                for (int ks = 0; ks < K_STEPS; ks++)
                    ldsm_x4(afrag[ks], A_base + a_off + ks * 32);
                need_afrag = false;
            }

            const uint32_t Bb = Bb0 + (t % 3) * B_TILE_BYTES + b_off;

            float acc[4][4];
            #pragma unroll
            for (int ni = 0; ni < 4; ni++)
                #pragma unroll
                for (int e = 0; e < 4; e++) acc[ni][e] = 0.0f;

            #pragma unroll
            for (int ks = 0; ks < K_STEPS; ks++) {
                uint32_t b01[4], b23[4];
                ldsm_x4(b01, Bb + ks * 32);
                ldsm_x4(b23, Bb + 16 * TSTRIDE_B + ks * 32);
                MMA16832F8(acc[0], afrag[ks], b01[0], b01[2]);
                MMA16832F8(acc[1], afrag[ks], b01[1], b01[3]);
                MMA16832F8(acc[2], afrag[ks], b23[0], b23[2]);
                MMA16832F8(acc[3], afrag[ks], b23[1], b23[3]);
            }

            // epilogue: v = ex2(acc) = exp(sim/tau); split diag / off-diag paths
            const int col0 = J * BN;
            float cs[8] = {0, 0, 0, 0, 0, 0, 0, 0};
            if ((J >> 2) == I) {             // diagonal block: row sums only
                #pragma unroll
                for (int ni = 0; ni < 4; ni++)
                    #pragma unroll
                    for (int e = 0; e < 4; e++) {
                        float v = ex2f(acc[ni][e]);
                        int r = row0 + (e >> 1) * 8 + (lane >> 2);
                        int c = col0 + ni * 8 + (lane & 3) * 2 + (e & 1);
                        if (c == r) v = 1.0f;            // diag -> exp(0)
                        denom[e >> 1] += v;
                    }
            } else {                         // off-diag: row sums + col sums
                #pragma unroll
                for (int ni = 0; ni < 4; ni++)
                    #pragma unroll
                    for (int e = 0; e < 4; e++) {
                        float v = ex2f(acc[ni][e]);
                        denom[e >> 1] += v;
                        cs[ni * 2 + (e & 1)] += v;
                    }
                // reduce col partials over row-carrying lane bits (2,3,4)
                #pragma unroll
                for (int k = 0; k < 8; k++) {
                    cs[k] += __shfl_xor_sync(0xffffffffu, cs[k], 4);
                    cs[k] += __shfl_xor_sync(0xffffffffu, cs[k], 8);
                    cs[k] += __shfl_xor_sync(0xffffffffu, cs[k], 16);
                }
                if (lane < 4) {
                    #pragma unroll
                    for (int k = 0; k < 8; k++)
                        atomicAdd(&g_denom[col0 + (k >> 1) * 8 + lane * 2 + (k & 1)],
                                  cs[k]);
                }
            }
        }

        // segment epilogue: flush row denominators, protect A/B for next segment
        #pragma unroll
        for (int d = 0; d < 2; d++) {
            denom[d] += __shfl_xor_sync(0xffffffffu, denom[d], 1);
            denom[d] += __shfl_xor_sync(0xffffffffu, denom[d], 2);
        }
        if ((lane & 3) == 0) {
            #pragma unroll
            for (int d = 0; d < 2; d++)
                atomicAdd(&g_denom[row0 + d * 8 + (lane >> 2)], denom[d]);
        }
        denom[0] = denom[1] = 0.0f;
        __syncthreads();                     // all reads of A done before reload
    }

    // ---- last CTA: final log/mean reduction ----
    __threadfence();
    __shared__ unsigned s_tick;
    if (tid == 0) s_tick = atomicAdd(&g_done, 1u);
    __syncthreads();
    if (s_tick == NUM_CTAS - 1) {
        float s = 0.0f;
        for (int r = tid; r < TWO_N; r += NTHREADS)
            s += logf(g_denom[r]) - g_pos[r & (NROWS - 1)] * 10.0f;
        #pragma unroll
        for (int o = 16; o; o >>= 1) s += __shfl_xor_sync(0xffffffffu, s, o);
        __shared__ float red[8];
        if (lane == 0) red[warp] = s;
        __syncthreads();
        if (tid == 0) {
            float v = 0.0f;
            #pragma unroll
            for (int w = 0; w < 8; w++) v += red[w];
            out[0] = v * (1.0f / (float)TWO_N);
        }
    }
}

// ---------------- launch ----------------------------------------------------
extern "C" void kernel_launch(void* const* d_in, const int* in_sizes, int n_in,
                              void* d_out, int out_size) {
    (void)in_sizes; (void)n_in; (void)out_size;
    const float* x1 = (const float*)d_in[0];
    const float* x2 = (const float*)d_in[1];
    float* out = (float*)d_out;

    cudaFuncSetAttribute(gemm_kernel,
                         cudaFuncAttributeMaxDynamicSharedMemorySize, SMEM_TOTAL);

    normpos_kernel<<<NROWS / 8, 256>>>(x1, x2);
    gemm_kernel<<<NUM_CTAS, NTHREADS, SMEM_TOTAL>>>(out);
}

// round 9
// speedup vs baseline: 1.0146x; 1.0142x over previous
#include <cuda_runtime.h>
#include <cuda_fp8.h>
#include <cstdint>

// ============================================================================
// ContrastiveLoss (N=4096, D=256, tau=0.1)
//   z = normalize(concat(x1,x2)) * sqrt(10*log2(e)) -> e4m3   (scale folded in)
//   acc = z'_r . z'_j = 14.427 * sim  ->  exp(sim/tau) = ex2(acc)
//   denom[r] = sum_j exp(...)  (diag -> exp(0)=1);  pos in exact fp32
// Triangle fused FP8 mma.sync GEMM, 128x32 tiles, warp tile 16x32.
// ROUND 9: register-diet build — no afrag cache, no cs[] array (acc reused
// in-place for column sums) so ptxas stays under the 128-reg clamp: the
// rounds 3-8 plateau was hot-loop spills (regs clamped + L1 34-44%).
// ============================================================================

static constexpr int NROWS = 4096;
static constexpr int TWO_N = 8192;
static constexpr int D     = 256;          // K
static constexpr int BM    = 128;          // rows per strip
static constexpr int BN    = 32;           // cols per tile
// pair p in [0,32): strip p (256-4p tiles) + strip 63-p (4p+4 tiles) = 260.
static constexpr int NUM_TILES = 8320;
static constexpr int NUM_CTAS  = 296;                // 2 per SM
static constexpr int K_STEPS   = D / 32;             // 8 (fp8 k=32 per mma)
static constexpr int NTHREADS  = 256;

// sqrt(10 * log2(e)) — folded into z so epilogue is a bare ex2
#define ZSCALE 3.79828214f

// SMEM: padded row stride 272 B (17 x 16B)
static constexpr int TSTRIDE_B = 272;
static constexpr int A_TILE_BYTES = BM * TSTRIDE_B;   // 34816
static constexpr int B_TILE_BYTES = BN * TSTRIDE_B;   // 8704
static constexpr int SMEM_TOTAL = A_TILE_BYTES + 3 * B_TILE_BYTES;  // 60928

// ---------------- device scratch (allocation-free) --------------------------
__device__ unsigned char g_z8[TWO_N * D];   // e4m3 (pre-scaled), [8192][256]
__device__ float    g_pos[NROWS];
__device__ float    g_denom[TWO_N];
__device__ unsigned g_done;

// ---------------- PTX helpers ----------------------------------------------
__device__ __forceinline__ uint32_t smem_to_u32(const void* p) {
    uint32_t a;
    asm("{ .reg .u64 t; cvta.to.shared.u64 t, %1; cvt.u32.u64 %0, t; }"
        : "=r"(a) : "l"(p));
    return a;
}

__device__ __forceinline__ void cp_async16(uint32_t dst, const void* src) {
    asm volatile("cp.async.cg.shared.global [%0], [%1], 16;"
                 :: "r"(dst), "l"(src) : "memory");
}
#define CP_COMMIT() asm volatile("cp.async.commit_group;" ::: "memory")
#define CP_WAIT1()  asm volatile("cp.async.wait_group 1;" ::: "memory")

__device__ __forceinline__ void ldsm_x4(uint32_t* r, uint32_t addr) {
    asm volatile("ldmatrix.sync.aligned.m8n8.x4.shared.b16 {%0,%1,%2,%3}, [%4];"
                 : "=r"(r[0]), "=r"(r[1]), "=r"(r[2]), "=r"(r[3]) : "r"(addr));
}

#define MMA16832F8(d, a, bx, by) \
    asm volatile( \
        "mma.sync.aligned.m16n8k32.row.col.f32.e4m3.e4m3.f32 " \
        "{%0,%1,%2,%3}, {%4,%5,%6,%7}, {%8,%9}, {%0,%1,%2,%3};" \
        : "+f"((d)[0]), "+f"((d)[1]), "+f"((d)[2]), "+f"((d)[3]) \
        : "r"((a)[0]), "r"((a)[1]), "r"((a)[2]), "r"((a)[3]), \
          "r"(bx), "r"(by))

__device__ __forceinline__ float ex2f(float x) {
    float r;
    asm("ex2.approx.ftz.f32 %0, %1;" : "=f"(r) : "f"(x));
    return r;
}

__device__ __forceinline__ uint32_t pack_e4m3x4(float v0, float v1, float v2, float v3) {
    __nv_fp8x2_storage_t lo =
        __nv_cvt_float2_to_fp8x2(make_float2(v0, v1), __NV_SATFINITE, __NV_E4M3);
    __nv_fp8x2_storage_t hi =
        __nv_cvt_float2_to_fp8x2(make_float2(v2, v3), __NV_SATFINITE, __NV_E4M3);
    return (uint32_t)lo | ((uint32_t)hi << 16);
}

// ---------------- Stage 1: fused normalize + pos (reads x1/x2 once) --------
__global__ void normpos_kernel(const float* __restrict__ x1, const float* __restrict__ x2) {
    int i    = blockIdx.x * 8 + (threadIdx.x >> 5);   // pair row 0..4095
    int lane = threadIdx.x & 31;
    if (blockIdx.x == 0 && threadIdx.x == 0) g_done = 0;

    const float4* s1 = reinterpret_cast<const float4*>(x1 + (size_t)i * D);
    const float4* s2 = reinterpret_cast<const float4*>(x2 + (size_t)i * D);
    float4 a0 = s1[lane * 2], a1 = s1[lane * 2 + 1];
    float4 b0 = s2[lane * 2], b1 = s2[lane * 2 + 1];

    float ss1 = a0.x * a0.x + a0.y * a0.y + a0.z * a0.z + a0.w * a0.w
              + a1.x * a1.x + a1.y * a1.y + a1.z * a1.z + a1.w * a1.w;
    float ss2 = b0.x * b0.x + b0.y * b0.y + b0.z * b0.z + b0.w * b0.w
              + b1.x * b1.x + b1.y * b1.y + b1.z * b1.z + b1.w * b1.w;
    float dot = a0.x * b0.x + a0.y * b0.y + a0.z * b0.z + a0.w * b0.w
              + a1.x * b1.x + a1.y * b1.y + a1.z * b1.z + a1.w * b1.w;
    #pragma unroll
    for (int o = 16; o; o >>= 1) {
        ss1 += __shfl_xor_sync(0xffffffffu, ss1, o);
        ss2 += __shfl_xor_sync(0xffffffffu, ss2, o);
        dot += __shfl_xor_sync(0xffffffffu, dot, o);
    }
    float inv1 = 1.0f / fmaxf(sqrtf(ss1), 1e-12f);
    float inv2 = 1.0f / fmaxf(sqrtf(ss2), 1e-12f);
    if (lane == 0) {
        g_pos[i] = dot * inv1 * inv2;     // exact fp32, unscaled
        g_denom[i] = 0.0f;
        g_denom[i + NROWS] = 0.0f;
    }
    float q1 = inv1 * ZSCALE, q2 = inv2 * ZSCALE;

    uint2 w1, w2;
    w1.x = pack_e4m3x4(a0.x * q1, a0.y * q1, a0.z * q1, a0.w * q1);
    w1.y = pack_e4m3x4(a1.x * q1, a1.y * q1, a1.z * q1, a1.w * q1);
    w2.x = pack_e4m3x4(b0.x * q2, b0.y * q2, b0.z * q2, b0.w * q2);
    w2.y = pack_e4m3x4(b1.x * q2, b1.y * q2, b1.z * q2, b1.w * q2);
    *reinterpret_cast<uint2*>(g_z8 + (size_t)i * D + lane * 8) = w1;
    *reinterpret_cast<uint2*>(g_z8 + (size_t)(i + NROWS) * D + lane * 8) = w2;
}

// ---------------- tile loaders (fp8 rows of 256 B) ---------------------------
__device__ __forceinline__ void load_A(uint32_t dst, int row0, int tid) {
    const unsigned char* src = g_z8 + (size_t)row0 * D;
    #pragma unroll
    for (int i = 0; i < 8; i++) {
        int idx = tid + i * NTHREADS;      // 2048 chunks of 16B
        int r = idx >> 4, s = idx & 15;
        cp_async16(dst + r * TSTRIDE_B + s * 16, src + r * D + s * 16);
    }
}
__device__ __forceinline__ void load_B(uint32_t dst, int row0, int tid) {
    const unsigned char* src = g_z8 + (size_t)row0 * D;
    #pragma unroll
    for (int i = 0; i < 2; i++) {
        int idx = tid + i * NTHREADS;      // 512 chunks of 16B
        int r = idx >> 4, s = idx & 15;
        cp_async16(dst + r * TSTRIDE_B + s * 16, src + r * D + s * 16);
    }
}

// ---------------- Stage 2: triangular fused FP8 GEMM + ex2 + sums -----------
__global__ __launch_bounds__(NTHREADS, 2)
void gemm_kernel(float* __restrict__ out) {
    extern __shared__ char smem[];
    const int tid  = threadIdx.x;
    const int lane = tid & 31;
    const int warp = tid >> 5;              // 0..7, owns rows warp*16..+16
    const int cta  = blockIdx.x;

    const uint32_t smem_u = smem_to_u32(smem);
    const uint32_t A_base = smem_u;
    const uint32_t Bb0 = smem_u + A_TILE_BYTES;

    const int t0 = (int)(((long long)cta * NUM_TILES) / NUM_CTAS);
    const int t1 = (int)(((long long)(cta + 1) * NUM_TILES) / NUM_CTAS);

    const uint32_t a_off = (uint32_t)((warp * 16 + (lane & 15)) * TSTRIDE_B
                                      + (lane >> 4) * 16);
    const uint32_t b_off = (uint32_t)((lane & 15) * TSTRIDE_B + (lane >> 4) * 16);

    float denom[2] = {0, 0};                // rows warp*16 + d*8 + lane>>2

    int t = t0;
    while (t < t1) {
        // decode segment: contiguous run of tiles sharing strip I
        int p   = t / 260;
        int idx = t - p * 260;
        int na  = 256 - 4 * p;
        int I, J, seg_end;
        if (idx < na) { I = p;      J = 4 * p + idx;             seg_end = 260 * p + na; }
        else          { I = 63 - p; J = 252 - 4 * p + (idx - na); seg_end = 260 * (p + 1); }
        const int te = (seg_end < t1) ? seg_end : t1;

        // segment prologue: A strip + first B tile (one group)
        load_A(A_base, I * BM, tid);
        load_B(Bb0 + (t % 3) * B_TILE_BYTES, J * BN, tid);
        CP_COMMIT();

        const int row0 = I * BM + warp * 16;

        for (; t < te; t++, J++) {
            if (t + 1 < te)
                load_B(Bb0 + ((t + 1) % 3) * B_TILE_BYTES, (J + 1) * BN, tid);
            CP_COMMIT();                     // possibly empty group
            CP_WAIT1();                      // retire group for tile t (and A)
            __syncthreads();                 // single barrier per tile

            const uint32_t Ab = A_base + a_off;
            const uint32_t Bb = Bb0 + (t % 3) * B_TILE_BYTES + b_off;

            float acc[4][4];
            #pragma unroll
            for (int ni = 0; ni < 4; ni++)
                #pragma unroll
                for (int e = 0; e < 4; e++) acc[ni][e] = 0.0f;

            #pragma unroll
            for (int ks = 0; ks < K_STEPS; ks++) {
                uint32_t a[4], b01[4], b23[4];
                ldsm_x4(a,   Ab + ks * 32);
                ldsm_x4(b01, Bb + ks * 32);
                ldsm_x4(b23, Bb + 16 * TSTRIDE_B + ks * 32);
                MMA16832F8(acc[0], a, b01[0], b01[2]);
                MMA16832F8(acc[1], a, b01[1], b01[3]);
                MMA16832F8(acc[2], a, b23[0], b23[2]);
                MMA16832F8(acc[3], a, b23[1], b23[3]);
            }

            // epilogue: v = ex2(acc) = exp(sim/tau); acc reused for col sums
            const int col0 = J * BN;
            if ((J >> 2) == I) {             // diagonal block: row sums only
                #pragma unroll
                for (int ni = 0; ni < 4; ni++)
                    #pragma unroll
                    for (int e = 0; e < 4; e++) {
                        float v = ex2f(acc[ni][e]);
                        int r = row0 + (e >> 1) * 8 + (lane >> 2);
                        int c = col0 + ni * 8 + (lane & 3) * 2 + (e & 1);
                        if (c == r) v = 1.0f;            // diag -> exp(0)
                        denom[e >> 1] += v;
                    }
            } else {                         // off-diag: row sums + col sums
                #pragma unroll
                for (int ni = 0; ni < 4; ni++) {
                    #pragma unroll
                    for (int e = 0; e < 4; e++) {
                        float v = ex2f(acc[ni][e]);
                        denom[e >> 1] += v;
                        acc[ni][e] = v;      // keep for column reduction
                    }
                    // fold the two row positions per column into slots 0,1
                    acc[ni][0] += acc[ni][2];
                    acc[ni][1] += acc[ni][3];
                }
                // reduce over row-carrying lane bits (2,3,4)
                #pragma unroll
                for (int ni = 0; ni < 4; ni++)
                    #pragma unroll
                    for (int h = 0; h < 2; h++) {
                        float x = acc[ni][h];
                        x += __shfl_xor_sync(0xffffffffu, x, 4);
                        x += __shfl_xor_sync(0xffffffffu, x, 8);
                        x += __shfl_xor_sync(0xffffffffu, x, 16);
                        acc[ni][h] = x;
                    }
                if (lane < 4) {
                    #pragma unroll
                    for (int ni = 0; ni < 4; ni++)
                        #pragma unroll
                        for (int h = 0; h < 2; h++)
                            atomicAdd(&g_denom[col0 + ni * 8 + lane * 2 + h],
                                      acc[ni][h]);
                }
            }
        }

        // segment epilogue: flush row denominators, protect A/B for next segment
        #pragma unroll
        for (int d = 0; d < 2; d++) {
            denom[d] += __shfl_xor_sync(0xffffffffu, denom[d], 1);
            denom[d] += __shfl_xor_sync(0xffffffffu, denom[d], 2);
        }
        if ((lane & 3) == 0) {
            #pragma unroll
            for (int d = 0; d < 2; d++)
                atomicAdd(&g_denom[row0 + d * 8 + (lane >> 2)], denom[d]);
        }
        denom[0] = denom[1] = 0.0f;
        __syncthreads();                     // all reads of A done before reload
    }

    // ---- last CTA: final log/mean reduction ----
    __threadfence();
    __shared__ unsigned s_tick;
    if (tid == 0) s_tick = atomicAdd(&g_done, 1u);
    __syncthreads();
    if (s_tick == NUM_CTAS - 1) {
        float s = 0.0f;
        for (int r = tid; r < TWO_N; r += NTHREADS)
            s += logf(g_denom[r]) - g_pos[r & (NROWS - 1)] * 10.0f;
        #pragma unroll
        for (int o = 16; o; o >>= 1) s += __shfl_xor_sync(0xffffffffu, s, o);
        __shared__ float red[8];
        if (lane == 0) red[warp] = s;
        __syncthreads();
        if (tid == 0) {
            float v = 0.0f;
            #pragma unroll
            for (int w = 0; w < 8; w++) v += red[w];
            out[0] = v * (1.0f / (float)TWO_N);
        }
    }
}

// ---------------- launch ----------------------------------------------------
extern "C" void kernel_launch(void* const* d_in, const int* in_sizes, int n_in,
                              void* d_out, int out_size) {
    (void)in_sizes; (void)n_in; (void)out_size;
    const float* x1 = (const float*)d_in[0];
    const float* x2 = (const float*)d_in[1];
    float* out = (float*)d_out;

    cudaFuncSetAttribute(gemm_kernel,
                         cudaFuncAttributeMaxDynamicSharedMemorySize, SMEM_TOTAL);

    normpos_kernel<<<NROWS / 8, 256>>>(x1, x2);
    gemm_kernel<<<NUM_CTAS, NTHREADS, SMEM_TOTAL>>>(out);
}